// round 16
// baseline (speedup 1.0000x reference)
#include <cuda_runtime.h>
#include <cuda_bf16.h>
#include <stdint.h>
#include <math.h>

#define N_TOK   4096
#define D_MODEL 1024
#define N_HEADS 16
#define HD      64
#define KV_DIM  2048

// ---------------- scratch (device globals; no allocation allowed) ----------
__device__ __nv_bfloat16 g_xh [N_TOK * D_MODEL];   // LN out, bf16 high
__device__ __nv_bfloat16 g_xl [N_TOK * D_MODEL];   // LN out, bf16 residual
__device__ __nv_bfloat16 g_aoh[N_TOK * D_MODEL];   // attn out, bf16 high
__device__ __nv_bfloat16 g_aol[N_TOK * D_MODEL];   // attn out, bf16 residual
__device__ __nv_bfloat16 g_wqh[D_MODEL * D_MODEL], g_wql[D_MODEL * D_MODEL];
__device__ __nv_bfloat16 g_wkh[KV_DIM * D_MODEL],  g_wkl[KV_DIM * D_MODEL];
__device__ __nv_bfloat16 g_woh[D_MODEL * D_MODEL], g_wol[D_MODEL * D_MODEL];
__device__ float g_qp[N_TOK * D_MODEL];            // q projection (fp32)
__device__ float g_kv[N_TOK * KV_DIM];             // kv projection (tf32-rounded)
__device__ float g_k2[N_TOK * D_MODEL];            // K repacked (dim pairs)
__device__ float g_v2[(N_TOK/2) * (2*D_MODEL)];    // V repacked (key pairs)

// ---------------------------------------------------------------------------
// helpers
// ---------------------------------------------------------------------------
__device__ __forceinline__ uint32_t f2tf32(float f) {
    uint32_t r;
    asm("cvt.rna.tf32.f32 %0, %1;" : "=r"(r) : "f"(f));
    return r;
}

__device__ __forceinline__ float ex2(float f) {
    float r;
    asm("ex2.approx.f32 %0, %1;" : "=f"(r) : "f"(f));
    return r;
}

__device__ __forceinline__ void mma_tf32(float c[4], const uint32_t a[4], const uint32_t b[2]) {
    asm volatile(
        "mma.sync.aligned.m16n8k8.row.col.f32.tf32.tf32.f32 "
        "{%0,%1,%2,%3}, {%4,%5,%6,%7}, {%8,%9}, {%0,%1,%2,%3};"
        : "+f"(c[0]), "+f"(c[1]), "+f"(c[2]), "+f"(c[3])
        : "r"(a[0]), "r"(a[1]), "r"(a[2]), "r"(a[3]), "r"(b[0]), "r"(b[1]));
}

__device__ __forceinline__ void mma_bf16(float c[4], const uint32_t a[4], const uint32_t b[2]) {
    asm volatile(
        "mma.sync.aligned.m16n8k16.row.col.f32.bf16.bf16.f32 "
        "{%0,%1,%2,%3}, {%4,%5,%6,%7}, {%8,%9}, {%0,%1,%2,%3};"
        : "+f"(c[0]), "+f"(c[1]), "+f"(c[2]), "+f"(c[3])
        : "r"(a[0]), "r"(a[1]), "r"(a[2]), "r"(a[3]), "r"(b[0]), "r"(b[1]));
}

__device__ __forceinline__ void cp_async16(uint32_t saddr, const void* gaddr) {
    asm volatile("cp.async.cg.shared.global [%0], [%1], 16;\n" :: "r"(saddr), "l"(gaddr));
}
#define CP_COMMIT() asm volatile("cp.async.commit_group;\n" ::: "memory")
#define CP_WAIT(n)  asm volatile("cp.async.wait_group %0;\n" :: "n"(n) : "memory")

// split helper: x -> (h, l) bf16 pair
__device__ __forceinline__ void split_bf(float x, __nv_bfloat16& h, __nv_bfloat16& l) {
    h = __float2bfloat16_rn(x);
    l = __float2bfloat16_rn(x - __bfloat162float(h));
}

// ---------------------------------------------------------------------------
// LayerNorm (writes split bf16 h/l directly)
// ---------------------------------------------------------------------------
__device__ __forceinline__ float block_allreduce(float v) {
    __shared__ float red[8];
    __shared__ float bc;
    #pragma unroll
    for (int m = 16; m >= 1; m >>= 1) v += __shfl_xor_sync(0xffffffffu, v, m);
    if ((threadIdx.x & 31) == 0) red[threadIdx.x >> 5] = v;
    __syncthreads();
    if (threadIdx.x == 0) {
        float t = 0.f;
        #pragma unroll
        for (int i = 0; i < 8; i++) t += red[i];
        bc = t;
    }
    __syncthreads();
    float r = bc;
    __syncthreads();
    return r;
}

__global__ __launch_bounds__(256) void ln_kernel(
    const float* __restrict__ q, const float* __restrict__ gamma,
    const float* __restrict__ beta,
    __nv_bfloat16* __restrict__ xh, __nv_bfloat16* __restrict__ xl)
{
    int row = blockIdx.x;
    int tid = threadIdx.x;
    const float4 v = ((const float4*)(q + (size_t)row * D_MODEL))[tid];

    float s = v.x + v.y + v.z + v.w;
    float mu = block_allreduce(s) * (1.0f / D_MODEL);

    float dx = v.x - mu, dy = v.y - mu, dz = v.z - mu, dw = v.w - mu;
    float var = block_allreduce(dx*dx + dy*dy + dz*dz + dw*dw) * (1.0f / D_MODEL);
    float rstd = rsqrtf(var + 1e-5f);

    const float4 g = ((const float4*)gamma)[tid];
    const float4 b = ((const float4*)beta)[tid];
    float o0 = dx * rstd * g.x + b.x;
    float o1 = dy * rstd * g.y + b.y;
    float o2 = dz * rstd * g.z + b.z;
    float o3 = dw * rstd * g.w + b.w;

    __nv_bfloat16 h0,h1,h2,h3,l0,l1,l2,l3;
    split_bf(o0,h0,l0); split_bf(o1,h1,l1); split_bf(o2,h2,l2); split_bf(o3,h3,l3);
    size_t base = (size_t)row * D_MODEL + tid * 4;
    __nv_bfloat162* ph = (__nv_bfloat162*)(xh + base);
    __nv_bfloat162* pl = (__nv_bfloat162*)(xl + base);
    ph[0] = __nv_bfloat162{h0,h1}; ph[1] = __nv_bfloat162{h2,h3};
    pl[0] = __nv_bfloat162{l0,l1}; pl[1] = __nv_bfloat162{l2,l3};
}

// ---------------------------------------------------------------------------
// Weight split: fp32 -> bf16 h/l
// ---------------------------------------------------------------------------
__global__ __launch_bounds__(256) void split_kernel(
    const float* __restrict__ w, __nv_bfloat16* __restrict__ wh,
    __nv_bfloat16* __restrict__ wl)
{
    int idx = (blockIdx.x * 256 + threadIdx.x) * 4;
    float4 v = *(const float4*)&w[idx];
    __nv_bfloat16 h0,h1,h2,h3,l0,l1,l2,l3;
    split_bf(v.x,h0,l0); split_bf(v.y,h1,l1); split_bf(v.z,h2,l2); split_bf(v.w,h3,l3);
    __nv_bfloat162* ph = (__nv_bfloat162*)(wh + idx);
    __nv_bfloat162* pl = (__nv_bfloat162*)(wl + idx);
    ph[0] = __nv_bfloat162{h0,h1}; ph[1] = __nv_bfloat162{h2,h3};
    pl[0] = __nv_bfloat162{l0,l1}; pl[1] = __nv_bfloat162{l2,l3};
}

// ---------------------------------------------------------------------------
// K repack: dim pairs adjacent; V repack: key pairs adjacent
// ---------------------------------------------------------------------------
__global__ __launch_bounds__(256) void repack_k_kernel(
    const float* __restrict__ kv, float* __restrict__ k2)
{
    int idx = blockIdx.x * 256 + threadIdx.x;
    int row = idx >> 10;
    int oc  = idx & 1023;
    int oj  = oc & 7;
    int j   = (oj & 1) ? (oj >> 1) + 4 : (oj >> 1);
    k2[idx] = kv[(size_t)row * KV_DIM + (oc & ~7) + j];
}

__global__ __launch_bounds__(256) void repack_v_kernel(
    const float* __restrict__ kv, float* __restrict__ v2)
{
    int idx = blockIdx.x * 256 + threadIdx.x;
    int w   = idx & 1;
    int n   = (idx >> 1) & 63;
    int h   = (idx >> 7) & 15;
    int p   = idx >> 11;
    int key = (p >> 2) * 8 + (p & 3) + w * 4;
    v2[idx] = kv[(size_t)key * KV_DIM + D_MODEL + h * 64 + n];
}

// ---------------------------------------------------------------------------
// GEMM (3xBF16, pre-split operands, 3-stage cp.async ring, 1 barrier/tile)
// C[M,N] = A[M,K] @ B[N,K]^T.  smem stage: 4 arrays of 128 rows x 8 words,
// row stride GST=12 words (48 B, multiple of 16 for cp.async alignment;
// frag loads 12g+q mod 32 all distinct -> conflict-free).
// ---------------------------------------------------------------------------
#define GST   12                         // words per row (16B-aligned rows)
#define GARR  (128 * GST)                // 1536 words per array
#define GSTAGE (4 * GARR)                // 6144 words per stage
#define GEMM_SMEM_BYTES (3 * GSTAGE * 4) // 73728 B

__global__ __launch_bounds__(256) void gemm_bf16x3_kernel(
    const __nv_bfloat16* __restrict__ Ah, const __nv_bfloat16* __restrict__ Al,
    const __nv_bfloat16* __restrict__ Bh, const __nv_bfloat16* __restrict__ Bl,
    float* __restrict__ C, int M, int N, int K, int round_out)
{
    extern __shared__ uint32_t sg[];

    const int tid  = threadIdx.x;
    const int lane = tid & 31;
    const int warp = tid >> 5;
    const int wm   = (warp >> 1) * 32;
    const int wn   = (warp & 1) * 64;
    const int g    = lane >> 2;
    const int q    = lane & 3;
    const int brow = blockIdx.y * 128;
    const int bcol = blockIdx.x * 128;

    const int lrow  = tid >> 1;      // 0..127
    const int lhalf = tid & 1;       // 8-elem half of the 16-k row

    const uint32_t smem_base = (uint32_t)__cvta_generic_to_shared(sg);

    float acc[2][8][4];
    #pragma unroll
    for (int mt = 0; mt < 2; mt++)
        #pragma unroll
        for (int nt = 0; nt < 8; nt++)
            #pragma unroll
            for (int i = 0; i < 4; i++) acc[mt][nt][i] = 0.f;

    const int NTK = K / 16;

    // prologue: prefetch k-tiles 0,1
    #pragma unroll
    for (int pre = 0; pre < 2; pre++) {
        uint32_t boff = (uint32_t)(pre * GSTAGE);
        size_t ga = (size_t)(brow + lrow) * K + pre * 16 + lhalf * 8;
        size_t gb = (size_t)(bcol + lrow) * K + pre * 16 + lhalf * 8;
        uint32_t soff = (boff + lrow * GST + lhalf * 4) * 4;
        cp_async16(smem_base + soff,                Ah + ga);
        cp_async16(smem_base + soff + GARR * 4,     Al + ga);
        cp_async16(smem_base + soff + 2 * GARR * 4, Bh + gb);
        cp_async16(smem_base + soff + 3 * GARR * 4, Bl + gb);
        CP_COMMIT();
    }

    int stage = 0;
    for (int t = 0; t < NTK; t++) {
        if (t == NTK - 1) { CP_WAIT(0); } else { CP_WAIT(1); }
        __syncthreads();

        if (t + 2 < NTK) {
            int pst = stage + 2; if (pst >= 3) pst -= 3;
            uint32_t boff = (uint32_t)(pst * GSTAGE);
            size_t ga = (size_t)(brow + lrow) * K + (t + 2) * 16 + lhalf * 8;
            size_t gb = (size_t)(bcol + lrow) * K + (t + 2) * 16 + lhalf * 8;
            uint32_t soff = (boff + lrow * GST + lhalf * 4) * 4;
            cp_async16(smem_base + soff,                Ah + ga);
            cp_async16(smem_base + soff + GARR * 4,     Al + ga);
            cp_async16(smem_base + soff + 2 * GARR * 4, Bh + gb);
            cp_async16(smem_base + soff + 3 * GARR * 4, Bl + gb);
            CP_COMMIT();
        }

        const uint32_t* sAh = sg + stage * GSTAGE;
        const uint32_t* sAl = sAh + GARR;
        const uint32_t* sBh = sAl + GARR;
        const uint32_t* sBl = sBh + GARR;

        uint32_t ah[2][4], al[2][4], bh[8][2], bl[8][2];
        #pragma unroll
        for (int mt = 0; mt < 2; mt++) {
            int r0 = wm + mt * 16 + g;
            ah[mt][0] = sAh[r0       * GST + q];
            ah[mt][1] = sAh[(r0 + 8) * GST + q];
            ah[mt][2] = sAh[r0       * GST + q + 4];
            ah[mt][3] = sAh[(r0 + 8) * GST + q + 4];
            al[mt][0] = sAl[r0       * GST + q];
            al[mt][1] = sAl[(r0 + 8) * GST + q];
            al[mt][2] = sAl[r0       * GST + q + 4];
            al[mt][3] = sAl[(r0 + 8) * GST + q + 4];
        }
        #pragma unroll
        for (int nt = 0; nt < 8; nt++) {
            int n0 = wn + nt * 8 + g;
            bh[nt][0] = sBh[n0 * GST + q];
            bh[nt][1] = sBh[n0 * GST + q + 4];
            bl[nt][0] = sBl[n0 * GST + q];
            bl[nt][1] = sBl[n0 * GST + q + 4];
        }
        #pragma unroll
        for (int mt = 0; mt < 2; mt++)
            #pragma unroll
            for (int nt = 0; nt < 8; nt++)
                mma_bf16(acc[mt][nt], ah[mt], bh[nt]);
        #pragma unroll
        for (int mt = 0; mt < 2; mt++)
            #pragma unroll
            for (int nt = 0; nt < 8; nt++)
                mma_bf16(acc[mt][nt], al[mt], bh[nt]);
        #pragma unroll
        for (int mt = 0; mt < 2; mt++)
            #pragma unroll
            for (int nt = 0; nt < 8; nt++)
                mma_bf16(acc[mt][nt], ah[mt], bl[nt]);

        stage = stage + 1; if (stage >= 3) stage = 0;
    }

    if (round_out) {
        #pragma unroll
        for (int mt = 0; mt < 2; mt++)
            #pragma unroll
            for (int nt = 0; nt < 8; nt++)
                #pragma unroll
                for (int i = 0; i < 4; i++)
                    acc[mt][nt][i] = __uint_as_float(f2tf32(acc[mt][nt][i]));
    }

    #pragma unroll
    for (int mt = 0; mt < 2; mt++) {
        int r0 = brow + wm + mt * 16 + g;
        #pragma unroll
        for (int nt = 0; nt < 8; nt++) {
            int cc = bcol + wn + nt * 8 + 2 * q;
            *(float2*)&C[(size_t)r0 * N + cc]       = make_float2(acc[mt][nt][0], acc[mt][nt][1]);
            *(float2*)&C[(size_t)(r0 + 8) * N + cc] = make_float2(acc[mt][nt][2], acc[mt][nt][3]);
        }
    }
}

// ---------------------------------------------------------------------------
// Flash attention: tf32 mma, 3-stage cp.async ring, one barrier per tile,
// anchor-free softmax in the exp2 domain (Q pre-scaled by log2e/8),
// LDS.64 K/V fragment pairs, split-bf16 epilogue for the Wo GEMM.
// ---------------------------------------------------------------------------
#define QS   68
#define KSD  72
#define VPD  136
#define NSTAGE 3
#define KOFF  (64 * KSD)
#define KVBUF (64 * KSD + 32 * VPD)
#define ATTN_SMEM_BYTES (NSTAGE * KVBUF * 4)

__global__ __launch_bounds__(256) void attn_tf32_kernel(
    const float* __restrict__ qp, const float* __restrict__ k2,
    const float* __restrict__ v2,
    __nv_bfloat16* __restrict__ aoh, __nv_bfloat16* __restrict__ aol)
{
    extern __shared__ uint32_t sm[];

    const int tid   = threadIdx.x;
    const int lane  = tid & 31;
    const int warp  = tid >> 5;
    const int g     = lane >> 2;
    const int q     = lane & 3;
    const int qbase = blockIdx.x * 128;
    const int hbase = blockIdx.y * HD;
    const int r0    = warp * 16 + g;
    const int l0    = g * 4 + (q >> 1);
    const int l1    = l0 + 2;
    const bool odd  = (q & 1);
    const float qscale = 0.125f * 1.44269504088896341f;  // 1/8 * log2(e)

    // ---- stage Q (scaled, rna tf32) ----
    #pragma unroll
    for (int r = 0; r < 8; r++) {
        int e   = tid + 256 * r;
        int row = e >> 4;
        int d4  = (e & 15) * 4;
        float4 v = *(const float4*)&qp[(size_t)(qbase + row) * D_MODEL + hbase + d4];
        sm[row * QS + d4 + 0] = f2tf32(v.x * qscale);
        sm[row * QS + d4 + 1] = f2tf32(v.y * qscale);
        sm[row * QS + d4 + 2] = f2tf32(v.z * qscale);
        sm[row * QS + d4 + 3] = f2tf32(v.w * qscale);
    }
    __syncthreads();

    uint32_t qf[8][4];
    #pragma unroll
    for (int kb = 0; kb < 8; kb++) {
        qf[kb][0] = sm[r0       * QS + kb * 8 + q];
        qf[kb][1] = sm[(r0 + 8) * QS + kb * 8 + q];
        qf[kb][2] = sm[r0       * QS + kb * 8 + q + 4];
        qf[kb][3] = sm[(r0 + 8) * QS + kb * 8 + q + 4];
    }
    __syncthreads();

    const uint32_t smem_base = (uint32_t)__cvta_generic_to_shared(sm);

    #pragma unroll
    for (int pre = 0; pre < 2; pre++) {
        uint32_t boff = (uint32_t)(pre * KVBUF);
        #pragma unroll
        for (int r = 0; r < 4; r++) {
            int e   = tid + 256 * r;
            int key = e >> 4;
            int c16 = e & 15;
            cp_async16(smem_base + (boff + key * KSD + c16 * 4) * 4,
                       k2 + (size_t)(pre * 64 + key) * D_MODEL + hbase + c16 * 4);
        }
        #pragma unroll
        for (int r = 0; r < 4; r++) {
            int e   = tid + 256 * r;
            int pr  = e >> 5;
            int c32 = e & 31;
            cp_async16(smem_base + (boff + KOFF + pr * VPD + c32 * 4) * 4,
                       v2 + (size_t)(pre * 32 + pr) * (2 * D_MODEL) + hbase * 2 + c32 * 4);
        }
        CP_COMMIT();
    }

    float o[8][4];
    #pragma unroll
    for (int nt = 0; nt < 8; nt++)
        #pragma unroll
        for (int i = 0; i < 4; i++) o[nt][i] = 0.f;
    float lsum0 = 0.f, lsum1 = 0.f;

    const int NT = N_TOK / 64;
    int stage = 0;

    for (int t = 0; t < NT; t++) {
        if (t == NT - 1) { CP_WAIT(0); } else { CP_WAIT(1); }
        __syncthreads();

        if (t + 2 < NT) {
            int pstage = stage + 2; if (pstage >= NSTAGE) pstage -= NSTAGE;
            uint32_t boff = (uint32_t)(pstage * KVBUF);
            #pragma unroll
            for (int r = 0; r < 4; r++) {
                int e   = tid + 256 * r;
                int key = e >> 4;
                int c16 = e & 15;
                cp_async16(smem_base + (boff + key * KSD + c16 * 4) * 4,
                           k2 + (size_t)((t + 2) * 64 + key) * D_MODEL + hbase + c16 * 4);
            }
            #pragma unroll
            for (int r = 0; r < 4; r++) {
                int e   = tid + 256 * r;
                int pr  = e >> 5;
                int c32 = e & 31;
                cp_async16(smem_base + (boff + KOFF + pr * VPD + c32 * 4) * 4,
                           v2 + (size_t)((t + 2) * 32 + pr) * (2 * D_MODEL) + hbase * 2 + c32 * 4);
            }
            CP_COMMIT();
        }

        const uint32_t* Ks = sm + stage * KVBUF;
        const uint32_t* Vs = Ks + KOFF;

        // ---- S = Q K^T (tf32) ----
        float s[8][4];
        #pragma unroll
        for (int nt = 0; nt < 8; nt++)
            #pragma unroll
            for (int i = 0; i < 4; i++) s[nt][i] = 0.f;

        #pragma unroll
        for (int kb = 0; kb < 8; kb++) {
            const uint32_t* krow = &Ks[g * KSD + kb * 8 + 2 * q];
            #pragma unroll
            for (int nt = 0; nt < 8; nt++) {
                uint2 kk = *(const uint2*)&krow[(nt * 8) * KSD];
                uint32_t bf[2] = {kk.x, kk.y};
                mma_tf32(s[nt], qf[kb], bf);
            }
        }

        // ---- anchor-free softmax in exp2 domain ----
        #pragma unroll
        for (int nt = 0; nt < 8; nt++) {
            s[nt][0] = ex2(s[nt][0]);
            s[nt][1] = ex2(s[nt][1]);
            s[nt][2] = ex2(s[nt][2]);
            s[nt][3] = ex2(s[nt][3]);
            lsum0 += s[nt][0] + s[nt][1];
            lsum1 += s[nt][2] + s[nt][3];
        }

        // ---- O += P V ----
        #pragma unroll
        for (int kb = 0; kb < 8; kb++) {
            float t0  = __shfl_sync(0xffffffffu, s[kb][0], l0);
            float t1  = __shfl_sync(0xffffffffu, s[kb][1], l0);
            float t2  = __shfl_sync(0xffffffffu, s[kb][2], l0);
            float t3  = __shfl_sync(0xffffffffu, s[kb][3], l0);
            float u0  = __shfl_sync(0xffffffffu, s[kb][0], l1);
            float u1  = __shfl_sync(0xffffffffu, s[kb][1], l1);
            float u2  = __shfl_sync(0xffffffffu, s[kb][2], l1);
            float u3  = __shfl_sync(0xffffffffu, s[kb][3], l1);
            uint32_t pa[4];
            pa[0] = f2tf32(odd ? t1 : t0);
            pa[1] = f2tf32(odd ? t3 : t2);
            pa[2] = f2tf32(odd ? u1 : u0);
            pa[3] = f2tf32(odd ? u3 : u2);

            const uint32_t* vrow = &Vs[(kb * 4 + q) * VPD + g * 2];
            #pragma unroll
            for (int nt = 0; nt < 8; nt++) {
                uint2 vv = *(const uint2*)&vrow[nt * 16];
                uint32_t vf[2] = {vv.x, vv.y};
                mma_tf32(o[nt], pa, vf);
            }
        }

        stage = stage + 1; if (stage >= NSTAGE) stage = 0;
    }

    // ---- epilogue: quad-reduce l, normalize, write split bf16 ----
    lsum0 += __shfl_xor_sync(0xffffffffu, lsum0, 1);
    lsum0 += __shfl_xor_sync(0xffffffffu, lsum0, 2);
    lsum1 += __shfl_xor_sync(0xffffffffu, lsum1, 1);
    lsum1 += __shfl_xor_sync(0xffffffffu, lsum1, 2);
    float inv0 = 1.0f / lsum0, inv1 = 1.0f / lsum1;
    #pragma unroll
    for (int nt = 0; nt < 8; nt++) {
        int col = hbase + nt * 8 + 2 * q;
        size_t base0 = (size_t)(qbase + r0) * D_MODEL + col;
        size_t base1 = (size_t)(qbase + r0 + 8) * D_MODEL + col;
        float a0 = o[nt][0] * inv0, a1 = o[nt][1] * inv0;
        float b0 = o[nt][2] * inv1, b1 = o[nt][3] * inv1;
        __nv_bfloat16 h0,h1,h2,h3,e0,e1,e2,e3;
        split_bf(a0,h0,e0); split_bf(a1,h1,e1);
        split_bf(b0,h2,e2); split_bf(b1,h3,e3);
        *(__nv_bfloat162*)(aoh + base0) = __nv_bfloat162{h0,h1};
        *(__nv_bfloat162*)(aol + base0) = __nv_bfloat162{e0,e1};
        *(__nv_bfloat162*)(aoh + base1) = __nv_bfloat162{h2,h3};
        *(__nv_bfloat162*)(aol + base1) = __nv_bfloat162{e2,e3};
    }
}

// ---------------------------------------------------------------------------
extern "C" void kernel_launch(void* const* d_in, const int* in_sizes, int n_in,
                              void* d_out, int out_size)
{
    (void)in_sizes; (void)n_in; (void)out_size;
    const float* q     = (const float*)d_in[0];
    const float* gamma = (const float*)d_in[1];
    const float* beta  = (const float*)d_in[2];
    const float* Wq    = (const float*)d_in[3];
    const float* Wkv   = (const float*)d_in[4];
    const float* Wo    = (const float*)d_in[5];
    float* out = (float*)d_out;

    __nv_bfloat16 *xh, *xl, *aoh, *aol, *wqh, *wql, *wkh, *wkl, *woh, *wol;
    float *qp, *kvb, *k2p, *v2p;
    cudaGetSymbolAddress((void**)&xh,  g_xh);
    cudaGetSymbolAddress((void**)&xl,  g_xl);
    cudaGetSymbolAddress((void**)&aoh, g_aoh);
    cudaGetSymbolAddress((void**)&aol, g_aol);
    cudaGetSymbolAddress((void**)&wqh, g_wqh);
    cudaGetSymbolAddress((void**)&wql, g_wql);
    cudaGetSymbolAddress((void**)&wkh, g_wkh);
    cudaGetSymbolAddress((void**)&wkl, g_wkl);
    cudaGetSymbolAddress((void**)&woh, g_woh);
    cudaGetSymbolAddress((void**)&wol, g_wol);
    cudaGetSymbolAddress((void**)&qp,  g_qp);
    cudaGetSymbolAddress((void**)&kvb, g_kv);
    cudaGetSymbolAddress((void**)&k2p, g_k2);
    cudaGetSymbolAddress((void**)&v2p, g_v2);

    cudaFuncSetAttribute(attn_tf32_kernel,
                         cudaFuncAttributeMaxDynamicSharedMemorySize, ATTN_SMEM_BYTES);
    cudaFuncSetAttribute(gemm_bf16x3_kernel,
                         cudaFuncAttributeMaxDynamicSharedMemorySize, GEMM_SMEM_BYTES);

    ln_kernel<<<N_TOK, 256>>>(q, gamma, beta, xh, xl);

    split_kernel<<<D_MODEL * D_MODEL / 1024, 256>>>(Wq,  wqh, wql);
    split_kernel<<<KV_DIM  * D_MODEL / 1024, 256>>>(Wkv, wkh, wkl);
    split_kernel<<<D_MODEL * D_MODEL / 1024, 256>>>(Wo,  woh, wol);

    gemm_bf16x3_kernel<<<dim3(D_MODEL/128, N_TOK/128), 256, GEMM_SMEM_BYTES>>>(
        xh, xl, wqh, wql, qp, N_TOK, D_MODEL, D_MODEL, 0);
    gemm_bf16x3_kernel<<<dim3(KV_DIM/128, N_TOK/128), 256, GEMM_SMEM_BYTES>>>(
        xh, xl, wkh, wkl, kvb, N_TOK, KV_DIM, D_MODEL, 1);

    repack_k_kernel<<<N_TOK * D_MODEL / 256, 256>>>(kvb, k2p);
    repack_v_kernel<<<N_TOK * D_MODEL / 256, 256>>>(kvb, v2p);

    attn_tf32_kernel<<<dim3(N_TOK/128, N_HEADS), 256, ATTN_SMEM_BYTES>>>(qp, k2p, v2p, aoh, aol);

    gemm_bf16x3_kernel<<<dim3(D_MODEL/128, N_TOK/128), 256, GEMM_SMEM_BYTES>>>(
        aoh, aol, woh, wol, out, N_TOK, D_MODEL, D_MODEL, 0);
}

// round 17
// speedup vs baseline: 1.1020x; 1.1020x over previous
#include <cuda_runtime.h>
#include <cuda_bf16.h>
#include <stdint.h>
#include <math.h>

#define N_TOK   4096
#define D_MODEL 1024
#define N_HEADS 16
#define HD      64
#define KV_DIM  2048

// ---------------- scratch (device globals; no allocation allowed) ----------
__device__ float g_x [N_TOK * D_MODEL];   // layernorm output
__device__ float g_qp[N_TOK * D_MODEL];   // q projection
__device__ float g_kv[N_TOK * KV_DIM];    // kv projection (tf32-rounded)
__device__ float g_k2[N_TOK * D_MODEL];   // K, dim-pairs interleaved per 8-group
__device__ float g_v2[(N_TOK/2) * (2*D_MODEL)]; // V, key-row pairs interleaved
__device__ float g_ao[N_TOK * D_MODEL];   // attention output

// ---------------------------------------------------------------------------
// helpers
// ---------------------------------------------------------------------------
__device__ __forceinline__ uint32_t f2tf32(float f) {
    uint32_t r;
    asm("cvt.rna.tf32.f32 %0, %1;" : "=r"(r) : "f"(f));
    return r;
}

__device__ __forceinline__ float ex2(float f) {
    float r;
    asm("ex2.approx.f32 %0, %1;" : "=f"(r) : "f"(f));
    return r;
}

__device__ __forceinline__ void mma_tf32(float c[4], const uint32_t a[4], const uint32_t b[2]) {
    asm volatile(
        "mma.sync.aligned.m16n8k8.row.col.f32.tf32.tf32.f32 "
        "{%0,%1,%2,%3}, {%4,%5,%6,%7}, {%8,%9}, {%0,%1,%2,%3};"
        : "+f"(c[0]), "+f"(c[1]), "+f"(c[2]), "+f"(c[3])
        : "r"(a[0]), "r"(a[1]), "r"(a[2]), "r"(a[3]), "r"(b[0]), "r"(b[1]));
}

__device__ __forceinline__ void mma_bf16(float c[4], const uint32_t a[4], const uint32_t b[2]) {
    asm volatile(
        "mma.sync.aligned.m16n8k16.row.col.f32.bf16.bf16.f32 "
        "{%0,%1,%2,%3}, {%4,%5,%6,%7}, {%8,%9}, {%0,%1,%2,%3};"
        : "+f"(c[0]), "+f"(c[1]), "+f"(c[2]), "+f"(c[3])
        : "r"(a[0]), "r"(a[1]), "r"(a[2]), "r"(a[3]), "r"(b[0]), "r"(b[1]));
}

__device__ __forceinline__ uint32_t pack_bf16(__nv_bfloat16 lo, __nv_bfloat16 hi) {
    __nv_bfloat162 t;
    t.x = lo; t.y = hi;
    return *reinterpret_cast<uint32_t*>(&t);
}

__device__ __forceinline__ void cp_async16(uint32_t saddr, const void* gaddr) {
    asm volatile("cp.async.cg.shared.global [%0], [%1], 16;\n" :: "r"(saddr), "l"(gaddr));
}
#define CP_COMMIT() asm volatile("cp.async.commit_group;\n" ::: "memory")
#define CP_WAIT(n)  asm volatile("cp.async.wait_group %0;\n" :: "n"(n) : "memory")

// ---------------------------------------------------------------------------
// LayerNorm
// ---------------------------------------------------------------------------
__device__ __forceinline__ float block_allreduce(float v) {
    __shared__ float red[8];
    __shared__ float bc;
    #pragma unroll
    for (int m = 16; m >= 1; m >>= 1) v += __shfl_xor_sync(0xffffffffu, v, m);
    if ((threadIdx.x & 31) == 0) red[threadIdx.x >> 5] = v;
    __syncthreads();
    if (threadIdx.x == 0) {
        float t = 0.f;
        #pragma unroll
        for (int i = 0; i < 8; i++) t += red[i];
        bc = t;
    }
    __syncthreads();
    float r = bc;
    __syncthreads();
    return r;
}

__global__ __launch_bounds__(256) void ln_kernel(
    const float* __restrict__ q, const float* __restrict__ gamma,
    const float* __restrict__ beta, float* __restrict__ x)
{
    int row = blockIdx.x;
    int tid = threadIdx.x;
    const float4 v = ((const float4*)(q + (size_t)row * D_MODEL))[tid];

    float s = v.x + v.y + v.z + v.w;
    float mu = block_allreduce(s) * (1.0f / D_MODEL);

    float dx = v.x - mu, dy = v.y - mu, dz = v.z - mu, dw = v.w - mu;
    float var = block_allreduce(dx*dx + dy*dy + dz*dz + dw*dw) * (1.0f / D_MODEL);
    float rstd = rsqrtf(var + 1e-5f);

    const float4 g = ((const float4*)gamma)[tid];
    const float4 b = ((const float4*)beta)[tid];
    float4 o;
    o.x = dx * rstd * g.x + b.x;
    o.y = dy * rstd * g.y + b.y;
    o.z = dz * rstd * g.z + b.z;
    o.w = dw * rstd * g.w + b.w;
    ((float4*)(x + (size_t)row * D_MODEL))[tid] = o;
}

// ---------------------------------------------------------------------------
// K repack: within each 8-dim group, new col order [0,4,1,5,2,6,3,7] so that
// the mma b-frag pair (q, q+4) sits at adjacent words (2q, 2q+1).
// ---------------------------------------------------------------------------
__global__ __launch_bounds__(256) void repack_k_kernel(
    const float* __restrict__ kv, float* __restrict__ k2)
{
    int idx = blockIdx.x * 256 + threadIdx.x;       // over output, coalesced
    int row = idx >> 10;
    int oc  = idx & 1023;
    int oj  = oc & 7;
    int j   = (oj & 1) ? (oj >> 1) + 4 : (oj >> 1); // inverse permutation
    k2[idx] = kv[(size_t)row * KV_DIM + (oc & ~7) + j];
}

// ---------------------------------------------------------------------------
// V repack: key-row pairs (r, r+4) within each 8-key group interleaved:
// v2[p][h][n][w] = V[group*8 + q + 4w][h*64+n],  p = group*4+q.
// ---------------------------------------------------------------------------
__global__ __launch_bounds__(256) void repack_v_kernel(
    const float* __restrict__ kv, float* __restrict__ v2)
{
    int idx = blockIdx.x * 256 + threadIdx.x;       // over output, coalesced
    int w   = idx & 1;
    int n   = (idx >> 1) & 63;
    int h   = (idx >> 7) & 15;
    int p   = idx >> 11;
    int key = (p >> 2) * 8 + (p & 3) + w * 4;
    v2[idx] = kv[(size_t)key * KV_DIM + D_MODEL + h * 64 + n];
}

// ---------------------------------------------------------------------------
// GEMM (3xBF16, register-pipelined, in-loop split): C[M,N] = A[M,K] @ B[N,K]^T
// (R14-proven structure; the pre-split cp.async variant regressed in R16.)
// ---------------------------------------------------------------------------
#define WS 12

__global__ __launch_bounds__(256) void gemm_bf16x3_kernel(
    const float* __restrict__ A, const float* __restrict__ B,
    float* __restrict__ C, int M, int N, int K, int round_out)
{
    __shared__ uint32_t Ah[128 * WS], Al[128 * WS];
    __shared__ uint32_t Bh[128 * WS], Bl[128 * WS];

    const int tid  = threadIdx.x;
    const int lane = tid & 31;
    const int warp = tid >> 5;
    const int wm   = (warp >> 1) * 32;
    const int wn   = (warp & 1) * 64;
    const int g    = lane >> 2;
    const int q    = lane & 3;
    const int brow = blockIdx.y * 128;
    const int bcol = blockIdx.x * 128;

    const int row0 = tid >> 2;
    const int row1 = row0 + 64;
    const int c4   = (tid & 3) * 4;
    const int w0   = (tid & 3) * 2;

    float acc[2][8][4];
    #pragma unroll
    for (int mt = 0; mt < 2; mt++)
        #pragma unroll
        for (int nt = 0; nt < 8; nt++)
            #pragma unroll
            for (int i = 0; i < 4; i++) acc[mt][nt][i] = 0.f;

    float4 va0 = *(const float4*)&A[(size_t)(brow + row0) * K + c4];
    float4 va1 = *(const float4*)&A[(size_t)(brow + row1) * K + c4];
    float4 vb0 = *(const float4*)&B[(size_t)(bcol + row0) * K + c4];
    float4 vb1 = *(const float4*)&B[(size_t)(bcol + row1) * K + c4];

    for (int k0 = 0; k0 < K; k0 += 16) {
        __syncthreads();
        {
            #define SPLIT_STORE(SH, SL, ROW, V)                                         \
            {                                                                            \
                __nv_bfloat16 h0 = __float2bfloat16_rn(V.x);                             \
                __nv_bfloat16 h1 = __float2bfloat16_rn(V.y);                             \
                __nv_bfloat16 h2 = __float2bfloat16_rn(V.z);                             \
                __nv_bfloat16 h3 = __float2bfloat16_rn(V.w);                             \
                __nv_bfloat16 l0 = __float2bfloat16_rn(V.x - __bfloat162float(h0));      \
                __nv_bfloat16 l1 = __float2bfloat16_rn(V.y - __bfloat162float(h1));      \
                __nv_bfloat16 l2 = __float2bfloat16_rn(V.z - __bfloat162float(h2));      \
                __nv_bfloat16 l3 = __float2bfloat16_rn(V.w - __bfloat162float(h3));      \
                *(uint2*)&SH[(ROW) * WS + w0] =                                          \
                    make_uint2(pack_bf16(h0, h1), pack_bf16(h2, h3));                    \
                *(uint2*)&SL[(ROW) * WS + w0] =                                          \
                    make_uint2(pack_bf16(l0, l1), pack_bf16(l2, l3));                    \
            }
            SPLIT_STORE(Ah, Al, row0, va0);
            SPLIT_STORE(Ah, Al, row1, va1);
            SPLIT_STORE(Bh, Bl, row0, vb0);
            SPLIT_STORE(Bh, Bl, row1, vb1);
            #undef SPLIT_STORE
        }
        __syncthreads();

        if (k0 + 16 < K) {
            va0 = *(const float4*)&A[(size_t)(brow + row0) * K + k0 + 16 + c4];
            va1 = *(const float4*)&A[(size_t)(brow + row1) * K + k0 + 16 + c4];
            vb0 = *(const float4*)&B[(size_t)(bcol + row0) * K + k0 + 16 + c4];
            vb1 = *(const float4*)&B[(size_t)(bcol + row1) * K + k0 + 16 + c4];
        }

        uint32_t ah[2][4], al[2][4], bh[8][2], bl[8][2];
        #pragma unroll
        for (int mt = 0; mt < 2; mt++) {
            int r0 = wm + mt * 16 + g;
            ah[mt][0] = Ah[r0       * WS + q];
            ah[mt][1] = Ah[(r0 + 8) * WS + q];
            ah[mt][2] = Ah[r0       * WS + q + 4];
            ah[mt][3] = Ah[(r0 + 8) * WS + q + 4];
            al[mt][0] = Al[r0       * WS + q];
            al[mt][1] = Al[(r0 + 8) * WS + q];
            al[mt][2] = Al[r0       * WS + q + 4];
            al[mt][3] = Al[(r0 + 8) * WS + q + 4];
        }
        #pragma unroll
        for (int nt = 0; nt < 8; nt++) {
            int n0 = wn + nt * 8 + g;
            bh[nt][0] = Bh[n0 * WS + q];
            bh[nt][1] = Bh[n0 * WS + q + 4];
            bl[nt][0] = Bl[n0 * WS + q];
            bl[nt][1] = Bl[n0 * WS + q + 4];
        }
        #pragma unroll
        for (int mt = 0; mt < 2; mt++)
            #pragma unroll
            for (int nt = 0; nt < 8; nt++)
                mma_bf16(acc[mt][nt], ah[mt], bh[nt]);
        #pragma unroll
        for (int mt = 0; mt < 2; mt++)
            #pragma unroll
            for (int nt = 0; nt < 8; nt++)
                mma_bf16(acc[mt][nt], al[mt], bh[nt]);
        #pragma unroll
        for (int mt = 0; mt < 2; mt++)
            #pragma unroll
            for (int nt = 0; nt < 8; nt++)
                mma_bf16(acc[mt][nt], ah[mt], bl[nt]);
    }

    if (round_out) {
        #pragma unroll
        for (int mt = 0; mt < 2; mt++)
            #pragma unroll
            for (int nt = 0; nt < 8; nt++)
                #pragma unroll
                for (int i = 0; i < 4; i++)
                    acc[mt][nt][i] = __uint_as_float(f2tf32(acc[mt][nt][i]));
    }

    #pragma unroll
    for (int mt = 0; mt < 2; mt++) {
        int r0 = brow + wm + mt * 16 + g;
        #pragma unroll
        for (int nt = 0; nt < 8; nt++) {
            int cc = bcol + wn + nt * 8 + 2 * q;
            *(float2*)&C[(size_t)r0 * N + cc]       = make_float2(acc[mt][nt][0], acc[mt][nt][1]);
            *(float2*)&C[(size_t)(r0 + 8) * N + cc] = make_float2(acc[mt][nt][2], acc[mt][nt][3]);
        }
    }
}

// ---------------------------------------------------------------------------
// Flash attention, tf32 mma, 3-stage cp.async ring, ONE barrier per tile.
// Anchor-free softmax in the exp2 domain (Q pre-scaled by log2(e)/8, raw
// ex2.approx -> saves the hidden FMUL inside __expf on the serial chain).
// K/V repacked in global so b-fragment pairs are adjacent -> LDS.64.
// Block = 256 thr (8 warps); warp w owns query rows 16w..16w+15; KV tile = 64.
// ---------------------------------------------------------------------------
#define QS   68
#define KSD  72
#define VPD  136
#define NSTAGE 3
#define KOFF  (64 * KSD)                           // 4608 words
#define KVBUF (64 * KSD + 32 * VPD)                // 8960 words per stage
#define ATTN_SMEM_BYTES (NSTAGE * KVBUF * 4)       // 107520 B

__global__ __launch_bounds__(256) void attn_tf32_kernel(
    const float* __restrict__ qp, const float* __restrict__ k2,
    const float* __restrict__ v2, float* __restrict__ ao)
{
    extern __shared__ uint32_t sm[];

    const int tid   = threadIdx.x;
    const int lane  = tid & 31;
    const int warp  = tid >> 5;
    const int g     = lane >> 2;
    const int q     = lane & 3;
    const int qbase = blockIdx.x * 128;
    const int hbase = blockIdx.y * HD;
    const int r0    = warp * 16 + g;
    const int l0    = g * 4 + (q >> 1);
    const int l1    = l0 + 2;
    const bool odd  = (q & 1);
    const float qscale = 0.125f * 1.44269504088896341f;  // (1/8) * log2(e)

    // ---- stage Q (scaled by log2e/8, rna tf32) ----
    #pragma unroll
    for (int r = 0; r < 8; r++) {
        int e   = tid + 256 * r;
        int row = e >> 4;
        int d4  = (e & 15) * 4;
        float4 v = *(const float4*)&qp[(size_t)(qbase + row) * D_MODEL + hbase + d4];
        sm[row * QS + d4 + 0] = f2tf32(v.x * qscale);
        sm[row * QS + d4 + 1] = f2tf32(v.y * qscale);
        sm[row * QS + d4 + 2] = f2tf32(v.z * qscale);
        sm[row * QS + d4 + 3] = f2tf32(v.w * qscale);
    }
    __syncthreads();

    uint32_t qf[8][4];
    #pragma unroll
    for (int kb = 0; kb < 8; kb++) {
        qf[kb][0] = sm[r0       * QS + kb * 8 + q];
        qf[kb][1] = sm[(r0 + 8) * QS + kb * 8 + q];
        qf[kb][2] = sm[r0       * QS + kb * 8 + q + 4];
        qf[kb][3] = sm[(r0 + 8) * QS + kb * 8 + q + 4];
    }
    __syncthreads();   // Q reads done; smem becomes the K/V ring

    const uint32_t smem_base = (uint32_t)__cvta_generic_to_shared(sm);

    // ---- prologue: prefetch tiles 0 and 1 into stages 0,1 ----
    #pragma unroll
    for (int pre = 0; pre < 2; pre++) {
        uint32_t boff = (uint32_t)(pre * KVBUF);
        #pragma unroll
        for (int r = 0; r < 4; r++) {      // K: 64 rows x 16 chunks
            int e   = tid + 256 * r;
            int key = e >> 4;
            int c16 = e & 15;
            cp_async16(smem_base + (boff + key * KSD + c16 * 4) * 4,
                       k2 + (size_t)(pre * 64 + key) * D_MODEL + hbase + c16 * 4);
        }
        #pragma unroll
        for (int r = 0; r < 4; r++) {      // V: 32 pair-rows x 32 chunks
            int e   = tid + 256 * r;
            int pr  = e >> 5;
            int c32 = e & 31;
            cp_async16(smem_base + (boff + KOFF + pr * VPD + c32 * 4) * 4,
                       v2 + (size_t)(pre * 32 + pr) * (2 * D_MODEL) + hbase * 2 + c32 * 4);
        }
        CP_COMMIT();
    }

    float o[8][4];
    #pragma unroll
    for (int nt = 0; nt < 8; nt++)
        #pragma unroll
        for (int i = 0; i < 4; i++) o[nt][i] = 0.f;
    float lsum0 = 0.f, lsum1 = 0.f;

    const int NT = N_TOK / 64;
    int stage = 0;

    for (int t = 0; t < NT; t++) {
        if (t == NT - 1) { CP_WAIT(0); } else { CP_WAIT(1); }
        __syncthreads();   // tile t visible; tile t-1 reads drained

        if (t + 2 < NT) {
            int pstage = stage + 2; if (pstage >= NSTAGE) pstage -= NSTAGE;
            uint32_t boff = (uint32_t)(pstage * KVBUF);
            #pragma unroll
            for (int r = 0; r < 4; r++) {
                int e   = tid + 256 * r;
                int key = e >> 4;
                int c16 = e & 15;
                cp_async16(smem_base + (boff + key * KSD + c16 * 4) * 4,
                           k2 + (size_t)((t + 2) * 64 + key) * D_MODEL + hbase + c16 * 4);
            }
            #pragma unroll
            for (int r = 0; r < 4; r++) {
                int e   = tid + 256 * r;
                int pr  = e >> 5;
                int c32 = e & 31;
                cp_async16(smem_base + (boff + KOFF + pr * VPD + c32 * 4) * 4,
                           v2 + (size_t)((t + 2) * 32 + pr) * (2 * D_MODEL) + hbase * 2 + c32 * 4);
            }
            CP_COMMIT();
        }

        const uint32_t* Ks = sm + stage * KVBUF;
        const uint32_t* Vs = Ks + KOFF;

        // ---- S = Q K^T (tf32, LDS.64 b-frags) ----
        float s[8][4];
        #pragma unroll
        for (int nt = 0; nt < 8; nt++)
            #pragma unroll
            for (int i = 0; i < 4; i++) s[nt][i] = 0.f;

        #pragma unroll
        for (int kb = 0; kb < 8; kb++) {
            const uint32_t* krow = &Ks[g * KSD + kb * 8 + 2 * q];
            #pragma unroll
            for (int nt = 0; nt < 8; nt++) {
                uint2 kk = *(const uint2*)&krow[(nt * 8) * KSD];
                uint32_t bf[2] = {kk.x, kk.y};
                mma_tf32(s[nt], qf[kb], bf);
            }
        }

        // ---- anchor-free softmax (exp2 domain) ----
        #pragma unroll
        for (int nt = 0; nt < 8; nt++) {
            s[nt][0] = ex2(s[nt][0]);
            s[nt][1] = ex2(s[nt][1]);
            s[nt][2] = ex2(s[nt][2]);
            s[nt][3] = ex2(s[nt][3]);
            lsum0 += s[nt][0] + s[nt][1];
            lsum1 += s[nt][2] + s[nt][3];
        }

        // ---- O += P V (tf32, LDS.64 paired V, P via shuffles) ----
        #pragma unroll
        for (int kb = 0; kb < 8; kb++) {
            float t0  = __shfl_sync(0xffffffffu, s[kb][0], l0);
            float t1  = __shfl_sync(0xffffffffu, s[kb][1], l0);
            float t2  = __shfl_sync(0xffffffffu, s[kb][2], l0);
            float t3  = __shfl_sync(0xffffffffu, s[kb][3], l0);
            float u0  = __shfl_sync(0xffffffffu, s[kb][0], l1);
            float u1  = __shfl_sync(0xffffffffu, s[kb][1], l1);
            float u2  = __shfl_sync(0xffffffffu, s[kb][2], l1);
            float u3  = __shfl_sync(0xffffffffu, s[kb][3], l1);
            uint32_t pa[4];
            pa[0] = f2tf32(odd ? t1 : t0);
            pa[1] = f2tf32(odd ? t3 : t2);
            pa[2] = f2tf32(odd ? u1 : u0);
            pa[3] = f2tf32(odd ? u3 : u2);

            const uint32_t* vrow = &Vs[(kb * 4 + q) * VPD + g * 2];
            #pragma unroll
            for (int nt = 0; nt < 8; nt++) {
                uint2 vv = *(const uint2*)&vrow[nt * 16];
                uint32_t vf[2] = {vv.x, vv.y};
                mma_tf32(o[nt], pa, vf);
            }
        }

        stage = stage + 1; if (stage >= NSTAGE) stage = 0;
    }

    // ---- epilogue: reduce l across the quad once, then normalize ----
    lsum0 += __shfl_xor_sync(0xffffffffu, lsum0, 1);
    lsum0 += __shfl_xor_sync(0xffffffffu, lsum0, 2);
    lsum1 += __shfl_xor_sync(0xffffffffu, lsum1, 1);
    lsum1 += __shfl_xor_sync(0xffffffffu, lsum1, 2);
    float inv0 = 1.0f / lsum0, inv1 = 1.0f / lsum1;
    #pragma unroll
    for (int nt = 0; nt < 8; nt++) {
        int col = hbase + nt * 8 + 2 * q;
        *(float2*)&ao[(size_t)(qbase + r0) * D_MODEL + col] =
            make_float2(o[nt][0] * inv0, o[nt][1] * inv0);
        *(float2*)&ao[(size_t)(qbase + r0 + 8) * D_MODEL + col] =
            make_float2(o[nt][2] * inv1, o[nt][3] * inv1);
    }
}

// ---------------------------------------------------------------------------
extern "C" void kernel_launch(void* const* d_in, const int* in_sizes, int n_in,
                              void* d_out, int out_size)
{
    (void)in_sizes; (void)n_in; (void)out_size;
    const float* q     = (const float*)d_in[0];
    const float* gamma = (const float*)d_in[1];
    const float* beta  = (const float*)d_in[2];
    const float* Wq    = (const float*)d_in[3];
    const float* Wkv   = (const float*)d_in[4];
    const float* Wo    = (const float*)d_in[5];
    float* out = (float*)d_out;

    float *x, *qp, *kvb, *k2p, *v2p, *ao;
    cudaGetSymbolAddress((void**)&x,   g_x);
    cudaGetSymbolAddress((void**)&qp,  g_qp);
    cudaGetSymbolAddress((void**)&kvb, g_kv);
    cudaGetSymbolAddress((void**)&k2p, g_k2);
    cudaGetSymbolAddress((void**)&v2p, g_v2);
    cudaGetSymbolAddress((void**)&ao,  g_ao);

    cudaFuncSetAttribute(attn_tf32_kernel,
                         cudaFuncAttributeMaxDynamicSharedMemorySize, ATTN_SMEM_BYTES);

    ln_kernel<<<N_TOK, 256>>>(q, gamma, beta, x);

    gemm_bf16x3_kernel<<<dim3(D_MODEL/128, N_TOK/128), 256>>>(x, Wq,  qp,  N_TOK, D_MODEL, D_MODEL, 0);
    gemm_bf16x3_kernel<<<dim3(KV_DIM/128,  N_TOK/128), 256>>>(x, Wkv, kvb, N_TOK, KV_DIM,  D_MODEL, 1);

    repack_k_kernel<<<N_TOK * D_MODEL / 256, 256>>>(kvb, k2p);
    repack_v_kernel<<<N_TOK * D_MODEL / 256, 256>>>(kvb, v2p);

    attn_tf32_kernel<<<dim3(N_TOK/128, N_HEADS), 256, ATTN_SMEM_BYTES>>>(qp, k2p, v2p, ao);

    gemm_bf16x3_kernel<<<dim3(D_MODEL/128, N_TOK/128), 256>>>(ao, Wo, out, N_TOK, D_MODEL, D_MODEL, 0);
}